// round 16
// baseline (speedup 1.0000x reference)
#include <cuda_runtime.h>
#include <cuda_bf16.h>
#include <math.h>
#include <cstdint>

// Problem constants (fixed by setup_inputs)
#define BB   2
#define TT   2048
#define CC   1024
#define HH   16
#define HKVV 4
#define DD   64
#define MM   (BB*TT)          // 4096 rows
#define KVD  (HKVV*DD)        // 256
#define NW   (CC + 2*KVD)     // 1536 fused qkv output rows

typedef __nv_bfloat16  bf16;
typedef __nv_bfloat162 bf162;

// ---------------- scratch (static device globals; no allocs allowed) --------
__device__ __align__(128) bf16 g_xh[MM * CC],  g_xl[MM * CC];
__device__ __align__(128) bf16 g_wfh[NW * CC], g_wfl[NW * CC];   // wq|wk|wv fused
__device__ __align__(128) bf16 g_wph[CC * CC], g_wpl[CC * CC];
__device__ __align__(128) bf16 g_qh[MM * CC],  g_ql[MM * CC];    // post norm/rope/scale
__device__ __align__(128) bf16 g_kh[MM * KVD], g_kl[MM * KVD];
__device__ __align__(128) bf16 g_vh[MM * KVD], g_vl[MM * KVD];
__device__ __align__(128) bf16 g_ah[MM * CC],  g_al[MM * CC];    // attention out
__device__ float g_cos[TT][8];
__device__ float g_sin[TT][8];

// ---------------- PTX helpers ------------------------------------------------
__device__ __forceinline__ void mma_bf16(
    float* c, uint32_t a0, uint32_t a1, uint32_t a2, uint32_t a3,
    uint32_t b0, uint32_t b1)
{
    asm volatile(
        "mma.sync.aligned.m16n8k16.row.col.f32.bf16.bf16.f32 "
        "{%0,%1,%2,%3}, {%4,%5,%6,%7}, {%8,%9}, {%0,%1,%2,%3};"
        : "+f"(c[0]), "+f"(c[1]), "+f"(c[2]), "+f"(c[3])
        : "r"(a0), "r"(a1), "r"(a2), "r"(a3), "r"(b0), "r"(b1));
}
__device__ __forceinline__ float fast_exp2(float x) {
    float y; asm("ex2.approx.f32 %0, %1;" : "=f"(y) : "f"(x)); return y;
}
__device__ __forceinline__ uint32_t smem_u32(const void* p) {
    uint32_t a;
    asm("{ .reg .u64 t; cvta.to.shared.u64 t, %1; cvt.u32.u64 %0, t; }"
        : "=r"(a) : "l"(p));
    return a;
}
__device__ __forceinline__ void ldsm_x4(
    uint32_t addr, uint32_t& r0, uint32_t& r1, uint32_t& r2, uint32_t& r3)
{
    asm volatile("ldmatrix.sync.aligned.m8n8.x4.shared.b16 {%0,%1,%2,%3}, [%4];"
                 : "=r"(r0), "=r"(r1), "=r"(r2), "=r"(r3) : "r"(addr));
}
__device__ __forceinline__ void ldsm_x4_t(
    uint32_t addr, uint32_t& r0, uint32_t& r1, uint32_t& r2, uint32_t& r3)
{
    asm volatile("ldmatrix.sync.aligned.m8n8.x4.trans.shared.b16 {%0,%1,%2,%3}, [%4];"
                 : "=r"(r0), "=r"(r1), "=r"(r2), "=r"(r3) : "r"(addr));
}
__device__ __forceinline__ void cp16(uint32_t dst, const void* src) {
    asm volatile("cp.async.cg.shared.global [%0], [%1], 16;" :: "r"(dst), "l"(src));
}
#define CP_COMMIT() asm volatile("cp.async.commit_group;" ::: "memory")
#define CP_WAIT1()  asm volatile("cp.async.wait_group 1;"  ::: "memory")
#define CP_WAIT0()  asm volatile("cp.async.wait_group 0;"  ::: "memory")

// split two fp32 into packed bf16x2 hi + lo(residual)
__device__ __forceinline__ void split2(float x, float y, uint32_t& hi, uint32_t& lo) {
    bf16 hx = __float2bfloat16_rn(x), hy = __float2bfloat16_rn(y);
    bf162 h2 = __halves2bfloat162(hx, hy);
    hi = *(uint32_t*)&h2;
    bf162 l2 = __floats2bfloat162_rn(x - __bfloat162float(hx),
                                     y - __bfloat162float(hy));
    lo = *(uint32_t*)&l2;
}

// ---------------- pre-convert: fp32 -> (hi, lo) bf16 ------------------------
__global__ void cvt_all_kernel(
    const float* __restrict__ x,  const float* __restrict__ wq,
    const float* __restrict__ wk, const float* __restrict__ wv,
    const float* __restrict__ wp)
{
    const int N0 = MM * CC / 4;
    const int N1 = N0 + CC * CC / 4;
    const int N2 = N1 + KVD * CC / 4;
    const int N3 = N2 + KVD * CC / 4;
    const int N4 = N3 + CC * CC / 4;
    int i = blockIdx.x * blockDim.x + threadIdx.x;
    if (i >= N4) return;
    const float* src; bf16* hi; bf16* lo; int q;
    if (i < N0)      { src = x;  hi = g_xh;  lo = g_xl;  q = i; }
    else if (i < N1) { src = wq; hi = g_wfh; lo = g_wfl; q = i - N0; }
    else if (i < N2) { src = wk; hi = g_wfh + (size_t)CC * CC;
                       lo = g_wfl + (size_t)CC * CC;               q = i - N1; }
    else if (i < N3) { src = wv; hi = g_wfh + (size_t)(CC + KVD) * CC;
                       lo = g_wfl + (size_t)(CC + KVD) * CC;       q = i - N2; }
    else             { src = wp; hi = g_wph; lo = g_wpl; q = i - N3; }
    float4 v = ((const float4*)src)[q];
    bf16 hx = __float2bfloat16_rn(v.x), hy = __float2bfloat16_rn(v.y);
    bf16 hz = __float2bfloat16_rn(v.z), hw = __float2bfloat16_rn(v.w);
    ((bf162*)hi)[2*q]   = __halves2bfloat162(hx, hy);
    ((bf162*)hi)[2*q+1] = __halves2bfloat162(hz, hw);
    ((bf162*)lo)[2*q]   = __floats2bfloat162_rn(v.x - __bfloat162float(hx),
                                                v.y - __bfloat162float(hy));
    ((bf162*)lo)[2*q+1] = __floats2bfloat162_rn(v.z - __bfloat162float(hz),
                                                v.w - __bfloat162float(hw));
}

// ---------------- GEMM: 128x64 tiles, bf16 cp.async + mma.sync + ldmatrix ----
#define SP      40                 // smem row stride (bf16 elems), conflict-free
#define GARR_A  (128 * SP)         // 5120 elems
#define GARR_B  (64 * SP)          // 2560 elems
#define GSTAGE  (2 * GARR_A + 2 * GARR_B)   // 15360 elems
#define GEMM_SMEM_BYTES (2 * GSTAGE * 2)    // 61440 B (2 stages)

__device__ __forceinline__ void gemm_issue(
    const bf16* Ah, const bf16* Al, const bf16* Bh, const bf16* Bl,
    uint32_t sb, int st, int ch)
{
    int tid = threadIdx.x;
    // A: 128 rows x 32 cols, 2 halves per row
    int r  = tid >> 1;
    int s0 = (tid & 1) * 16;
    size_t goA = (size_t)r * CC + ch * 32 + s0;
    uint32_t dA = sb + (uint32_t)(st * GSTAGE + r * SP + s0) * 2;
    cp16(dA,                Ah + goA);
    cp16(dA + 16,           Ah + goA + 8);
    cp16(dA + GARR_A*2,     Al + goA);
    cp16(dA + GARR_A*2 + 16, Al + goA + 8);
    // B: 64 rows x 32 cols, 4 quarters per row
    int r2 = tid >> 2;
    int q  = (tid & 3) * 8;
    size_t goB = (size_t)r2 * CC + ch * 32 + q;
    uint32_t dB = sb + (uint32_t)(st * GSTAGE + 2 * GARR_A + r2 * SP + q) * 2;
    cp16(dB,            Bh + goB);
    cp16(dB + GARR_B*2, Bl + goB);
}

// one k16 step; term-major issue (per-accumulator order unchanged)
__device__ __forceinline__ void gemm_compute_k16(
    uint32_t sA, uint32_t sB, uint32_t aoff, uint32_t boff, int kk, float* acc)
{
    const uint32_t LOA = GARR_A * 2;
    const uint32_t LOB = GARR_B * 2;
    uint32_t bfh[4], bfl[4];
    {
        uint32_t ab = sB + boff + (uint32_t)kk * 2;
        ldsm_x4(ab,       bfh[0], bfh[1], bfh[2], bfh[3]);
        ldsm_x4(ab + LOB, bfl[0], bfl[1], bfl[2], bfl[3]);
    }
#pragma unroll
    for (int i = 0; i < 4; i++) {
        uint32_t aa = sA + aoff + (uint32_t)(i * 16 * SP + kk) * 2;
        uint32_t a0, a1, a2, a3, l0, l1, l2, l3;
        ldsm_x4(aa,       a0, a1, a2, a3);
        ldsm_x4(aa + LOA, l0, l1, l2, l3);
#pragma unroll
        for (int j = 0; j < 2; j++)
            mma_bf16(acc + (i*2 + j)*4, a0, a1, a2, a3, bfh[2*j], bfh[2*j+1]);
#pragma unroll
        for (int j = 0; j < 2; j++)
            mma_bf16(acc + (i*2 + j)*4, a0, a1, a2, a3, bfl[2*j], bfl[2*j+1]);
#pragma unroll
        for (int j = 0; j < 2; j++)
            mma_bf16(acc + (i*2 + j)*4, l0, l1, l2, l3, bfh[2*j], bfh[2*j+1]);
    }
}

// modes: 0 = fp32 out (proj), 1 = V split out, 2 = Q norm+rope+gain out,
//        3 = K norm+rope out.  Tile = 128 x 64 (one head wide for modes 2/3).
__device__ __forceinline__ void bf16_gemm_body(
    const bf16* Ah, const bf16* Al, const bf16* Bh, const bf16* Bl,
    float* Y, int ldy, int m0, int n0y, int mode, const float* qgain)
{
    extern __shared__ bf16 gsm[];
    uint32_t sb = smem_u32(gsm);
    int tid = threadIdx.x, wid = tid >> 5, lane = tid & 31;
    int g = lane >> 2, tg = lane & 3;
    int mbase = (wid & 1) * 64;
    int nbase = (wid >> 1) * 16;

    uint32_t aoff = (uint32_t)((mbase + (lane & 15)) * SP + ((lane >> 4) & 1) * 8) * 2;
    uint32_t boff = (uint32_t)(2 * GARR_A
                    + (nbase + (lane & 7) + ((lane & 16) ? 8 : 0)) * SP
                    + ((lane & 8) ? 8 : 0)) * 2;

    float acc[32];
#pragma unroll
    for (int i = 0; i < 32; i++) acc[i] = 0.f;

    gemm_issue(Ah, Al, Bh, Bl, sb, 0, 0);
    CP_COMMIT();

#pragma unroll 1
    for (int ch = 0; ch < 32; ch++) {
        int st = ch & 1;
        if (ch < 31) {
            gemm_issue(Ah, Al, Bh, Bl, sb, st ^ 1, ch + 1);
            CP_COMMIT();
            CP_WAIT1();
        } else {
            CP_WAIT0();
        }
        __syncthreads();
        uint32_t sA = sb + (uint32_t)(st * GSTAGE) * 2;
        gemm_compute_k16(sA, sA, aoff, boff, 0, acc);
        gemm_compute_k16(sA, sA, aoff, boff, 16, acc);
        __syncthreads();
    }

    if (mode <= 1) {
#pragma unroll
        for (int i = 0; i < 4; i++) {
#pragma unroll
            for (int j = 0; j < 2; j++) {
                float* c = acc + (i*2 + j) * 4;
                int mrow = m0 + mbase + i*16 + g;
                int ncol = n0y + nbase + j*8 + tg*2;
                if (mode == 0) {
                    *(float2*)&Y[(size_t)mrow * ldy + ncol]       = make_float2(c[0], c[1]);
                    *(float2*)&Y[(size_t)(mrow + 8) * ldy + ncol] = make_float2(c[2], c[3]);
                } else {
                    uint32_t ph, pl;
                    split2(c[0], c[1], ph, pl);
                    *(uint32_t*)&g_vh[(size_t)mrow * KVD + ncol] = ph;
                    *(uint32_t*)&g_vl[(size_t)mrow * KVD + ncol] = pl;
                    split2(c[2], c[3], ph, pl);
                    *(uint32_t*)&g_vh[(size_t)(mrow + 8) * KVD + ncol] = ph;
                    *(uint32_t*)&g_vl[(size_t)(mrow + 8) * KVD + ncol] = pl;
                }
            }
        }
        return;
    }

    // ---- fused RMS-norm + partial RoPE (+qgain) epilogue (modes 2/3) ----
    // CTA covers exactly ONE head (64 cols). Warps {b, b+2, b+4, b+6} with
    // b = wid&1 share an m-range and together span the head's 64 cols.
    float* smsum = (float*)gsm;          // [8 warps][64 rows]
#pragma unroll
    for (int i = 0; i < 4; i++) {
        float s0 = 0.f, s1 = 0.f;
#pragma unroll
        for (int j = 0; j < 2; j++) {
            float* c = acc + (i*2 + j) * 4;
            s0 += c[0]*c[0] + c[1]*c[1];
            s1 += c[2]*c[2] + c[3]*c[3];
        }
        s0 += __shfl_xor_sync(0xffffffffu, s0, 1);
        s0 += __shfl_xor_sync(0xffffffffu, s0, 2);
        s1 += __shfl_xor_sync(0xffffffffu, s1, 1);
        s1 += __shfl_xor_sync(0xffffffffu, s1, 2);
        if (tg == 0) {
            smsum[wid * 64 + i*16 + g]     = s0;
            smsum[wid * 64 + i*16 + g + 8] = s1;
        }
    }
    __syncthreads();
    int wb = wid & 1;
    bool dorope = (nbase == 0);           // warp covers head cols 0..15 (RoPE dims)
    float qsc = (mode == 2)
        ? qgain[n0y >> 6] * 0.125f * 1.4426950408889634f : 1.f;

#pragma unroll
    for (int i = 0; i < 4; i++) {
        int rl = i*16 + g;
        float t0 = smsum[wb*64 + rl]     + smsum[(wb+2)*64 + rl]
                 + smsum[(wb+4)*64 + rl] + smsum[(wb+6)*64 + rl];
        float t1 = smsum[wb*64 + rl + 8]     + smsum[(wb+2)*64 + rl + 8]
                 + smsum[(wb+4)*64 + rl + 8] + smsum[(wb+6)*64 + rl + 8];
        float a0 = t0 * (1.0f/64.0f) + 1.1920929e-07f;
        float a1 = t1 * (1.0f/64.0f) + 1.1920929e-07f;
        float r0 = rsqrtf(a0); r0 = r0 * (1.5f - 0.5f * a0 * r0 * r0);
        float r1 = rsqrtf(a1); r1 = r1 * (1.5f - 0.5f * a1 * r1 * r1);
#pragma unroll
        for (int j = 0; j < 2; j++) {
            float* c = acc + (i*2 + j) * 4;
            c[0] *= r0; c[1] *= r0; c[2] *= r1; c[3] *= r1;
        }
        if (dorope) {
            int mrow = m0 + mbase + i*16 + g;
            int ta = mrow & (TT - 1), tb = (mrow + 8) & (TT - 1);
            float* c0 = acc + (i*2 + 0) * 4;   // cols 2tg, 2tg+1 (x1)
            float* c1 = acc + (i*2 + 1) * 4;   // cols 8+2tg, 8+2tg+1 (x2)
            int d0 = 2*tg, d1 = 2*tg + 1;
            float ca0 = g_cos[ta][d0], sa0 = g_sin[ta][d0];
            float ca1 = g_cos[ta][d1], sa1 = g_sin[ta][d1];
            float cb0 = g_cos[tb][d0], sb0 = g_sin[tb][d0];
            float cb1 = g_cos[tb][d1], sb1 = g_sin[tb][d1];
            float x1, x2;
            x1 = c0[0]; x2 = c1[0]; c0[0] = x1*ca0 + x2*sa0; c1[0] = x2*ca0 - x1*sa0;
            x1 = c0[1]; x2 = c1[1]; c0[1] = x1*ca1 + x2*sa1; c1[1] = x2*ca1 - x1*sa1;
            x1 = c0[2]; x2 = c1[2]; c0[2] = x1*cb0 + x2*sb0; c1[2] = x2*cb0 - x1*sb0;
            x1 = c0[3]; x2 = c1[3]; c0[3] = x1*cb1 + x2*sb1; c1[3] = x2*cb1 - x1*sb1;
        }
        if (mode == 2) {
#pragma unroll
            for (int j = 0; j < 2; j++) {
                float* c = acc + (i*2 + j) * 4;
                c[0] *= qsc; c[1] *= qsc; c[2] *= qsc; c[3] *= qsc;
            }
        }
    }

    bf16* dh = (mode == 2) ? g_qh : g_kh;
    bf16* dl = (mode == 2) ? g_ql : g_kl;
#pragma unroll
    for (int i = 0; i < 4; i++) {
#pragma unroll
        for (int j = 0; j < 2; j++) {
            float* c = acc + (i*2 + j) * 4;
            int mrow = m0 + mbase + i*16 + g;
            int ncol = n0y + nbase + j*8 + tg*2;
            uint32_t ph, pl;
            split2(c[0], c[1], ph, pl);
            *(uint32_t*)&dh[(size_t)mrow * ldy + ncol] = ph;
            *(uint32_t*)&dl[(size_t)mrow * ldy + ncol] = pl;
            split2(c[2], c[3], ph, pl);
            *(uint32_t*)&dh[(size_t)(mrow + 8) * ldy + ncol] = ph;
            *(uint32_t*)&dl[(size_t)(mrow + 8) * ldy + ncol] = pl;
        }
    }
}

__global__ __launch_bounds__(256, 2) void qkv_gemm_kernel(const float* __restrict__ qgain) {
    int m0 = blockIdx.x * 128;
    int n0 = blockIdx.y * 64;
    const bf16* Ah = g_xh + (size_t)m0 * CC;
    const bf16* Al = g_xl + (size_t)m0 * CC;
    const bf16* Bh = g_wfh + (size_t)n0 * CC;
    const bf16* Bl = g_wfl + (size_t)n0 * CC;
    if (n0 < CC)
        bf16_gemm_body(Ah, Al, Bh, Bl, nullptr, CC, m0, n0, 2, qgain);           // Q
    else if (n0 < CC + KVD)
        bf16_gemm_body(Ah, Al, Bh, Bl, nullptr, KVD, m0, n0 - CC, 3, nullptr);   // K
    else
        bf16_gemm_body(Ah, Al, Bh, Bl, nullptr, KVD, m0, n0 - CC - KVD, 1, nullptr); // V
}

__global__ __launch_bounds__(256, 2) void proj_gemm_kernel(float* __restrict__ out) {
    int m0 = blockIdx.x * 128;
    int n0 = blockIdx.y * 64;
    bf16_gemm_body(g_ah + (size_t)m0 * CC, g_al + (size_t)m0 * CC,
                   g_wph + (size_t)n0 * CC, g_wpl + (size_t)n0 * CC,
                   out, CC, m0, n0, 0, nullptr);
}

// ---------------- RoPE table (double precision of fp32 angle) ---------------
__global__ void rope_table_kernel() {
    int idx = blockIdx.x * blockDim.x + threadIdx.x;
    if (idx >= TT * 8) return;
    int t = idx >> 3;
    int i = idx & 7;
    double inv_d = exp2(-((double)(2 * i) / 64.0) * 13.28771237954945);
    float inv_f = (float)inv_d;
    float ang = (float)t * inv_f;
    g_cos[t][i] = (float)cos((double)ang);
    g_sin[t][i] = (float)sin((double)ang);
}

// ---------------- flash attention v2: Q in smem, 32-key tiles, 2 CTA/SM ------
#define ASP   72                   // smem row stride (bf16 elems)
#define QARR  (128 * ASP)          // 9216 elems per Q array
#define AKR   32                   // keys per tile
#define AARR  (AKR * ASP)          // 2304 elems per K/V array
#define ASTG  (4 * AARR)           // per stage
#define ATTN_SMEM_BYTES ((2 * QARR + 2 * ASTG) * 2)   // 73728 B

__device__ __forceinline__ void attn_issue(
    const bf16* kh, const bf16* kl, const bf16* vh, const bf16* vl,
    uint32_t sb, int st, int k0)
{
    int tid = threadIdx.x;
    int r   = tid >> 3;                  // key row 0..31
    int s0  = tid & 7;                   // seg 0..7
    size_t go = (size_t)(k0 + r) * KVD + s0 * 8;
    uint32_t d = sb + (uint32_t)(2 * QARR + st * ASTG + r * ASP + s0 * 8) * 2;
    const uint32_t AB = AARR * 2;
    cp16(d,        kh + go);
    cp16(d + AB,   kl + go);
    cp16(d + 2*AB, vh + go);
    cp16(d + 3*AB, vl + go);
}

__device__ __forceinline__ void attn_issue_q(
    const bf16* qh, const bf16* ql, uint32_t sb, int row0)
{
    int tid = threadIdx.x;
    int r   = tid >> 1;                  // q row 0..127
    int s0  = (tid & 1) * 4;             // segs s0..s0+3
    size_t go = (size_t)(row0 + r) * CC + s0 * 8;
    uint32_t d = sb + (uint32_t)(r * ASP + s0 * 8) * 2;
#pragma unroll
    for (int i = 0; i < 4; i++) {
        cp16(d + i * 16,            qh + go + i * 8);
        cp16(d + QARR * 2 + i * 16, ql + go + i * 8);
    }
}

__global__ __launch_bounds__(256, 2) void attn_kernel(const int* __restrict__ wl_ptr) {
    extern __shared__ bf16 asm_[];
    uint32_t sb = smem_u32(asm_);

    int tid  = threadIdx.x;
    int w    = tid >> 5;
    int lane = tid & 31;
    int g    = lane >> 2, tg = lane & 3;
    int ln15 = lane & 15;

    int h  = blockIdx.x & 15;
    int b  = blockIdx.x >> 4;
    int q0 = (int)(gridDim.y - 1 - blockIdx.y) * 128;
    int kvh = h >> 2;

    int wl = *wl_ptr;
    if (wl < 0) wl = TT;

    int qr0   = q0 + w * 16 + g;
    int qr1   = qr0 + 8;
    int qrmin = q0 + w * 16;
    int qrmax = qrmin + 15;

    uint32_t qoff = (uint32_t)((w * 16 + (lane & 15)) * ASP
                               + ((lane >> 4) & 1) * 8) * 2;
    uint32_t koff = (uint32_t)(((lane & 7) + ((lane & 16) ? 8 : 0)) * ASP
                               + ((lane & 8) ? 8 : 0)) * 2;

    float O[8][4];
#pragma unroll
    for (int j = 0; j < 8; j++)
#pragma unroll
        for (int c = 0; c < 4; c++) O[j][c] = 0.f;
    float m0 = -INFINITY, m1 = -INFINITY, l0 = 0.f, l1 = 0.f;

    int lo_b = q0 - wl;
    int kt_lo = (lo_b > 0) ? (lo_b / AKR) : 0;
    int kt_hi = (q0 + 127) / AKR;

    const bf16* kh = g_kh + (size_t)b * TT * KVD + kvh * DD;
    const bf16* kl = g_kl + (size_t)b * TT * KVD + kvh * DD;
    const bf16* vh = g_vh + (size_t)b * TT * KVD + kvh * DD;
    const bf16* vl = g_vl + (size_t)b * TT * KVD + kvh * DD;

    attn_issue_q(g_qh + (size_t)h * DD, g_ql + (size_t)h * DD, sb, b * TT + q0);
    attn_issue(kh, kl, vh, vl, sb, kt_lo & 1, kt_lo * AKR);
    CP_COMMIT();

#pragma unroll 1
    for (int kt = kt_lo; kt <= kt_hi; kt++) {
        int st = kt & 1;
        int k0 = kt * AKR;
        if (kt < kt_hi) {
            attn_issue(kh, kl, vh, vl, sb, st ^ 1, k0 + AKR);
            CP_COMMIT();
            CP_WAIT1();
        } else {
            CP_WAIT0();
        }
        __syncthreads();

        bool live = !(k0 > qrmax || k0 + AKR - 1 < qrmin - wl);
        if (live) {
            uint32_t kh_a = sb + (uint32_t)(2 * QARR + st * ASTG) * 2;
            uint32_t vh_b = kh_a + 2 * AARR * 2;
            const uint32_t ALO = AARR * 2;
            const uint32_t QLO = QARR * 2;

            float S[4][4];
#pragma unroll
            for (int j = 0; j < 4; j++)
#pragma unroll
                for (int c = 0; c < 4; c++) S[j][c] = 0.f;
#pragma unroll
            for (int s = 0; s < 4; s++) {
                uint32_t aq0, aq1, aq2, aq3, al0, al1, al2, al3;
                ldsm_x4(sb + qoff + s * 32,       aq0, aq1, aq2, aq3);
                ldsm_x4(sb + qoff + QLO + s * 32, al0, al1, al2, al3);
#pragma unroll
                for (int jp = 0; jp < 2; jp++) {
                    uint32_t ab = kh_a + koff + (uint32_t)(jp * 16 * ASP) * 2 + s * 32;
                    uint32_t h0, h1, h2, h3, e0, e1, e2, e3;
                    ldsm_x4(ab,       h0, h1, h2, h3);
                    ldsm_x4(ab + ALO, e0, e1, e2, e3);
                    mma_bf16(S[2*jp],   aq0, aq1, aq2, aq3, h0, h1);
                    mma_bf16(S[2*jp+1], aq0, aq1, aq2, aq3, h2, h3);
                    mma_bf16(S[2*jp],   aq0, aq1, aq2, aq3, e0, e1);
                    mma_bf16(S[2*jp+1], aq0, aq1, aq2, aq3, e2, e3);
                    mma_bf16(S[2*jp],   al0, al1, al2, al3, h0, h1);
                    mma_bf16(S[2*jp+1], al0, al1, al2, al3, h2, h3);
                }
            }

            float mc0 = -INFINITY, mc1 = -INFINITY;
#pragma unroll
            for (int j = 0; j < 4; j++) {
                int kj = k0 + 8 * j + 2 * tg;
                if (!(kj     <= qr0 && qr0 - kj     <= wl)) S[j][0] = -INFINITY;
                if (!(kj + 1 <= qr0 && qr0 - kj - 1 <= wl)) S[j][1] = -INFINITY;
                if (!(kj     <= qr1 && qr1 - kj     <= wl)) S[j][2] = -INFINITY;
                if (!(kj + 1 <= qr1 && qr1 - kj - 1 <= wl)) S[j][3] = -INFINITY;
                mc0 = fmaxf(mc0, fmaxf(S[j][0], S[j][1]));
                mc1 = fmaxf(mc1, fmaxf(S[j][2], S[j][3]));
            }
            mc0 = fmaxf(mc0, __shfl_xor_sync(0xffffffffu, mc0, 1));
            mc0 = fmaxf(mc0, __shfl_xor_sync(0xffffffffu, mc0, 2));
            mc1 = fmaxf(mc1, __shfl_xor_sync(0xffffffffu, mc1, 1));
            mc1 = fmaxf(mc1, __shfl_xor_sync(0xffffffffu, mc1, 2));

            if (mc0 > -INFINITY) {
                float mn = fmaxf(m0, mc0);
                float corr = fast_exp2(m0 - mn);
                m0 = mn; l0 *= corr;
                float sum = 0.f;
#pragma unroll
                for (int j = 0; j < 8; j++) { O[j][0] *= corr; O[j][1] *= corr; }
#pragma unroll
                for (int j = 0; j < 4; j++) {
                    S[j][0] = fast_exp2(S[j][0] - m0);
                    S[j][1] = fast_exp2(S[j][1] - m0);
                    sum += S[j][0] + S[j][1];
                }
                l0 += sum;
            } else {
#pragma unroll
                for (int j = 0; j < 4; j++) { S[j][0] = 0.f; S[j][1] = 0.f; }
            }
            if (mc1 > -INFINITY) {
                float mn = fmaxf(m1, mc1);
                float corr = fast_exp2(m1 - mn);
                m1 = mn; l1 *= corr;
                float sum = 0.f;
#pragma unroll
                for (int j = 0; j < 8; j++) { O[j][2] *= corr; O[j][3] *= corr; }
#pragma unroll
                for (int j = 0; j < 4; j++) {
                    S[j][2] = fast_exp2(S[j][2] - m1);
                    S[j][3] = fast_exp2(S[j][3] - m1);
                    sum += S[j][2] + S[j][3];
                }
                l1 += sum;
            } else {
#pragma unroll
                for (int j = 0; j < 4; j++) { S[j][2] = 0.f; S[j][3] = 0.f; }
            }

            uint32_t pah[2][4], pal[2][4];
#pragma unroll
            for (int s2 = 0; s2 < 2; s2++) {
                split2(S[2*s2][0],   S[2*s2][1],   pah[s2][0], pal[s2][0]);
                split2(S[2*s2][2],   S[2*s2][3],   pah[s2][1], pal[s2][1]);
                split2(S[2*s2+1][0], S[2*s2+1][1], pah[s2][2], pal[s2][2]);
                split2(S[2*s2+1][2], S[2*s2+1][3], pah[s2][3], pal[s2][3]);
            }
#pragma unroll
            for (int s2 = 0; s2 < 2; s2++) {
                uint32_t rowh4 = vh_b + (uint32_t)((16 * s2 + ln15) * (ASP * 2))
                               + ((uint32_t)(lane >> 4) << 4);
#pragma unroll
                for (int j = 0; j < 8; j += 2) {
                    uint32_t bh0, bh1, bh2, bh3, bl0, bl1, bl2, bl3;
                    ldsm_x4_t(rowh4 + 16 * j,       bh0, bh1, bh2, bh3);
                    ldsm_x4_t(rowh4 + ALO + 16 * j, bl0, bl1, bl2, bl3);
                    mma_bf16(O[j],   pah[s2][0], pah[s2][1], pah[s2][2], pah[s2][3], bh0, bh1);
                    mma_bf16(O[j+1], pah[s2][0], pah[s2][1], pah[s2][2], pah[s2][3], bh2, bh3);
                    mma_bf16(O[j],   pah[s2][0], pah[s2][1], pah[s2][2], pah[s2][3], bl0, bl1);
                    mma_bf16(O[j+1], pah[s2][0], pah[s2][1], pah[s2][2], pah[s2][3], bl2, bl3);
                    mma_bf16(O[j],   pal[s2][0], pal[s2][1], pal[s2][2], pal[s2][3], bh0, bh1);
                    mma_bf16(O[j+1], pal[s2][0], pal[s2][1], pal[s2][2], pal[s2][3], bh2, bh3);
                }
            }
        }
        __syncthreads();
    }

    l0 += __shfl_xor_sync(0xffffffffu, l0, 1);
    l0 += __shfl_xor_sync(0xffffffffu, l0, 2);
    l1 += __shfl_xor_sync(0xffffffffu, l1, 1);
    l1 += __shfl_xor_sync(0xffffffffu, l1, 2);
    float inv0 = 1.0f / l0;
    float inv1 = 1.0f / l1;
    size_t ro0 = (size_t)(b * TT + qr0) * CC + h * DD;
    size_t ro1 = ro0 + 8 * CC;
#pragma unroll
    for (int j = 0; j < 8; j++) {
        int col = 8 * j + 2 * tg;
        uint32_t ph, pl;
        split2(O[j][0] * inv0, O[j][1] * inv0, ph, pl);
        *(uint32_t*)&g_ah[ro0 + col] = ph;
        *(uint32_t*)&g_al[ro0 + col] = pl;
        split2(O[j][2] * inv1, O[j][3] * inv1, ph, pl);
        *(uint32_t*)&g_ah[ro1 + col] = ph;
        *(uint32_t*)&g_al[ro1 + col] = pl;
    }
}

// ---------------- launch -----------------------------------------------------
extern "C" void kernel_launch(void* const* d_in, const int* in_sizes, int n_in,
                              void* d_out, int out_size) {
    const float* x     = (const float*)d_in[0];
    const float* wq    = (const float*)d_in[1];
    const float* wk    = (const float*)d_in[2];
    const float* wv    = (const float*)d_in[3];
    const float* wproj = (const float*)d_in[4];
    const float* qgain = (const float*)d_in[5];
    const int*   wl    = (const int*)d_in[6];
    float* out = (float*)d_out;

    cudaFuncSetAttribute(qkv_gemm_kernel,
                         cudaFuncAttributeMaxDynamicSharedMemorySize, GEMM_SMEM_BYTES);
    cudaFuncSetAttribute(proj_gemm_kernel,
                         cudaFuncAttributeMaxDynamicSharedMemorySize, GEMM_SMEM_BYTES);
    cudaFuncSetAttribute(attn_kernel,
                         cudaFuncAttributeMaxDynamicSharedMemorySize, ATTN_SMEM_BYTES);

    rope_table_kernel<<<(TT * 8 + 255) / 256, 256>>>();

    const int NQUAD = MM*CC/4 + CC*CC/4 + KVD*CC/4 + KVD*CC/4 + CC*CC/4;
    cvt_all_kernel<<<(NQUAD + 255) / 256, 256>>>(x, wq, wk, wv, wproj);

    dim3 g1(MM / 128, NW / 64);                // 32 x 24
    qkv_gemm_kernel<<<g1, 256, GEMM_SMEM_BYTES>>>(qgain);

    dim3 g2(HH * BB, TT / 128);                // 32 x 16
    attn_kernel<<<g2, 256, ATTN_SMEM_BYTES>>>(wl);

    dim3 g3(MM / 128, CC / 64);                // 32 x 16
    proj_gemm_kernel<<<g3, 256, GEMM_SMEM_BYTES>>>(out);
}

// round 17
// speedup vs baseline: 1.1235x; 1.1235x over previous
#include <cuda_runtime.h>
#include <cuda_bf16.h>
#include <math.h>
#include <cstdint>

// Problem constants (fixed by setup_inputs)
#define BB   2
#define TT   2048
#define CC   1024
#define HH   16
#define HKVV 4
#define DD   64
#define MM   (BB*TT)          // 4096 rows
#define KVD  (HKVV*DD)        // 256
#define NW   (CC + 2*KVD)     // 1536 fused qkv output rows

typedef __nv_bfloat16  bf16;
typedef __nv_bfloat162 bf162;

// ---------------- scratch (static device globals; no allocs allowed) --------
__device__ __align__(128) bf16 g_xh[MM * CC],  g_xl[MM * CC];
__device__ __align__(128) bf16 g_wfh[NW * CC], g_wfl[NW * CC];   // wq|wk|wv fused
__device__ __align__(128) bf16 g_wph[CC * CC], g_wpl[CC * CC];
__device__ __align__(128) bf16 g_qh[MM * CC],  g_ql[MM * CC];    // post norm/rope/scale
__device__ __align__(128) bf16 g_kh[MM * KVD], g_kl[MM * KVD];
__device__ __align__(128) bf16 g_vh[MM * KVD], g_vl[MM * KVD];
__device__ __align__(128) bf16 g_ah[MM * CC],  g_al[MM * CC];    // attention out
__device__ float g_cos[TT][8];
__device__ float g_sin[TT][8];

// ---------------- PTX helpers ------------------------------------------------
__device__ __forceinline__ void mma_bf16(
    float* c, uint32_t a0, uint32_t a1, uint32_t a2, uint32_t a3,
    uint32_t b0, uint32_t b1)
{
    asm volatile(
        "mma.sync.aligned.m16n8k16.row.col.f32.bf16.bf16.f32 "
        "{%0,%1,%2,%3}, {%4,%5,%6,%7}, {%8,%9}, {%0,%1,%2,%3};"
        : "+f"(c[0]), "+f"(c[1]), "+f"(c[2]), "+f"(c[3])
        : "r"(a0), "r"(a1), "r"(a2), "r"(a3), "r"(b0), "r"(b1));
}
__device__ __forceinline__ float fast_exp2(float x) {
    float y; asm("ex2.approx.f32 %0, %1;" : "=f"(y) : "f"(x)); return y;
}
__device__ __forceinline__ uint32_t smem_u32(const void* p) {
    uint32_t a;
    asm("{ .reg .u64 t; cvta.to.shared.u64 t, %1; cvt.u32.u64 %0, t; }"
        : "=r"(a) : "l"(p));
    return a;
}
__device__ __forceinline__ void ldsm_x4(
    uint32_t addr, uint32_t& r0, uint32_t& r1, uint32_t& r2, uint32_t& r3)
{
    asm volatile("ldmatrix.sync.aligned.m8n8.x4.shared.b16 {%0,%1,%2,%3}, [%4];"
                 : "=r"(r0), "=r"(r1), "=r"(r2), "=r"(r3) : "r"(addr));
}
__device__ __forceinline__ void ldsm_x4_t(
    uint32_t addr, uint32_t& r0, uint32_t& r1, uint32_t& r2, uint32_t& r3)
{
    asm volatile("ldmatrix.sync.aligned.m8n8.x4.trans.shared.b16 {%0,%1,%2,%3}, [%4];"
                 : "=r"(r0), "=r"(r1), "=r"(r2), "=r"(r3) : "r"(addr));
}
__device__ __forceinline__ void cp16(uint32_t dst, const void* src) {
    asm volatile("cp.async.cg.shared.global [%0], [%1], 16;" :: "r"(dst), "l"(src));
}
#define CP_COMMIT() asm volatile("cp.async.commit_group;" ::: "memory")
#define CP_WAIT1()  asm volatile("cp.async.wait_group 1;"  ::: "memory")
#define CP_WAIT0()  asm volatile("cp.async.wait_group 0;"  ::: "memory")

// split two fp32 into packed bf16x2 hi + lo(residual)
__device__ __forceinline__ void split2(float x, float y, uint32_t& hi, uint32_t& lo) {
    bf16 hx = __float2bfloat16_rn(x), hy = __float2bfloat16_rn(y);
    bf162 h2 = __halves2bfloat162(hx, hy);
    hi = *(uint32_t*)&h2;
    bf162 l2 = __floats2bfloat162_rn(x - __bfloat162float(hx),
                                     y - __bfloat162float(hy));
    lo = *(uint32_t*)&l2;
}

// ---------------- pre-convert: fp32 -> (hi, lo) bf16 ------------------------
__global__ void cvt_all_kernel(
    const float* __restrict__ x,  const float* __restrict__ wq,
    const float* __restrict__ wk, const float* __restrict__ wv,
    const float* __restrict__ wp)
{
    const int N0 = MM * CC / 4;
    const int N1 = N0 + CC * CC / 4;
    const int N2 = N1 + KVD * CC / 4;
    const int N3 = N2 + KVD * CC / 4;
    const int N4 = N3 + CC * CC / 4;
    int i = blockIdx.x * blockDim.x + threadIdx.x;
    if (i >= N4) return;
    const float* src; bf16* hi; bf16* lo; int q;
    if (i < N0)      { src = x;  hi = g_xh;  lo = g_xl;  q = i; }
    else if (i < N1) { src = wq; hi = g_wfh; lo = g_wfl; q = i - N0; }
    else if (i < N2) { src = wk; hi = g_wfh + (size_t)CC * CC;
                       lo = g_wfl + (size_t)CC * CC;               q = i - N1; }
    else if (i < N3) { src = wv; hi = g_wfh + (size_t)(CC + KVD) * CC;
                       lo = g_wfl + (size_t)(CC + KVD) * CC;       q = i - N2; }
    else             { src = wp; hi = g_wph; lo = g_wpl; q = i - N3; }
    float4 v = ((const float4*)src)[q];
    bf16 hx = __float2bfloat16_rn(v.x), hy = __float2bfloat16_rn(v.y);
    bf16 hz = __float2bfloat16_rn(v.z), hw = __float2bfloat16_rn(v.w);
    ((bf162*)hi)[2*q]   = __halves2bfloat162(hx, hy);
    ((bf162*)hi)[2*q+1] = __halves2bfloat162(hz, hw);
    ((bf162*)lo)[2*q]   = __floats2bfloat162_rn(v.x - __bfloat162float(hx),
                                                v.y - __bfloat162float(hy));
    ((bf162*)lo)[2*q+1] = __floats2bfloat162_rn(v.z - __bfloat162float(hz),
                                                v.w - __bfloat162float(hw));
}

// ---------------- GEMM: pure-bf16 cp.async pipeline + mma.sync + ldmatrix ----
#define SP     40                 // smem row stride (bf16 elems), conflict-free
#define GARR   (128 * SP)         // 5120 elems per array
#define GSTAGE (4 * GARR)         // Ah,Al,Bh,Bl
#define GEMM_SMEM_BYTES (2 * GSTAGE * 2)   // 81920 B (2 stages)

__device__ __forceinline__ void gemm_issue(
    const bf16* Ah, const bf16* Al, const bf16* Bh, const bf16* Bl,
    uint32_t sb, int st, int ch)
{
    int tid = threadIdx.x;
    int r   = tid >> 1;
    int s0  = (tid & 1) * 2;
    size_t go = (size_t)r * CC + ch * 32 + s0 * 8;
    uint32_t d = sb + (uint32_t)(st * GSTAGE + r * SP + s0 * 8) * 2;
    const uint32_t AB = GARR * 2;
    cp16(d,               Ah + go);
    cp16(d + 16,          Ah + go + 8);
    cp16(d + AB,          Al + go);
    cp16(d + AB + 16,     Al + go + 8);
    cp16(d + 2*AB,        Bh + go);
    cp16(d + 2*AB + 16,   Bh + go + 8);
    cp16(d + 3*AB,        Bl + go);
    cp16(d + 3*AB + 16,   Bl + go + 8);
}

__device__ __forceinline__ void gemm_compute_k16(
    uint32_t sA, uint32_t sB, uint32_t aoff, uint32_t boff, int kk, float* acc)
{
    const uint32_t LO = GARR * 2;
    uint32_t bfh[8], bfl[8];
#pragma unroll
    for (int jp = 0; jp < 2; jp++) {
        uint32_t ab = sB + boff + (uint32_t)(jp * 16 * SP + kk) * 2;
        ldsm_x4(ab,      bfh[4*jp], bfh[4*jp+1], bfh[4*jp+2], bfh[4*jp+3]);
        ldsm_x4(ab + LO, bfl[4*jp], bfl[4*jp+1], bfl[4*jp+2], bfl[4*jp+3]);
    }
#pragma unroll
    for (int i = 0; i < 4; i++) {
        uint32_t aa = sA + aoff + (uint32_t)(i * 16 * SP + kk) * 2;
        uint32_t a0, a1, a2, a3, l0, l1, l2, l3;
        ldsm_x4(aa,      a0, a1, a2, a3);
        ldsm_x4(aa + LO, l0, l1, l2, l3);
#pragma unroll
        for (int j = 0; j < 4; j++)   // term 1: Ah*Bh
            mma_bf16(acc + (i*4 + j)*4, a0, a1, a2, a3, bfh[2*j], bfh[2*j+1]);
#pragma unroll
        for (int j = 0; j < 4; j++)   // term 2: Ah*Bl
            mma_bf16(acc + (i*4 + j)*4, a0, a1, a2, a3, bfl[2*j], bfl[2*j+1]);
#pragma unroll
        for (int j = 0; j < 4; j++)   // term 3: Al*Bh
            mma_bf16(acc + (i*4 + j)*4, l0, l1, l2, l3, bfh[2*j], bfh[2*j+1]);
    }
}

// modes: 0 = fp32 out (proj), 1 = V split out, 2 = Q norm+rope+gain out,
//        3 = K norm+rope out
__device__ __forceinline__ void bf16_gemm_body(
    const bf16* Ah, const bf16* Al, const bf16* Bh, const bf16* Bl,
    float* Y, int ldy, int m0, int n0y, int mode, const float* qgain)
{
    extern __shared__ bf16 gsm[];
    uint32_t sb = smem_u32(gsm);
    int tid = threadIdx.x, wid = tid >> 5, lane = tid & 31;
    int g = lane >> 2, tg = lane & 3;
    int mbase = (wid & 1) * 64;
    int nbase = (wid >> 1) * 32;

    uint32_t aoff = (uint32_t)((mbase + (lane & 15)) * SP + ((lane >> 4) & 1) * 8) * 2;
    uint32_t boff = (uint32_t)((nbase + (lane & 7) + ((lane & 16) ? 8 : 0)) * SP
                               + ((lane & 8) ? 8 : 0)) * 2;

    float acc[64];
#pragma unroll
    for (int i = 0; i < 64; i++) acc[i] = 0.f;

    gemm_issue(Ah, Al, Bh, Bl, sb, 0, 0);
    CP_COMMIT();

#pragma unroll 1
    for (int ch = 0; ch < 32; ch++) {
        int st = ch & 1;
        if (ch < 31) {
            gemm_issue(Ah, Al, Bh, Bl, sb, st ^ 1, ch + 1);
            CP_COMMIT();
            CP_WAIT1();
        } else {
            CP_WAIT0();
        }
        __syncthreads();
        uint32_t sA = sb + (uint32_t)(st * GSTAGE) * 2;
        uint32_t sB = sA + 2 * GARR * 2;
        gemm_compute_k16(sA, sB, aoff, boff, 0, acc);
        gemm_compute_k16(sA, sB, aoff, boff, 16, acc);
        __syncthreads();
    }

    if (mode <= 1) {
#pragma unroll
        for (int i = 0; i < 4; i++) {
#pragma unroll
            for (int j = 0; j < 4; j++) {
                float* c = acc + (i*4 + j) * 4;
                int mrow = m0 + mbase + i*16 + g;
                int ncol = n0y + nbase + j*8 + tg*2;
                if (mode == 0) {
                    *(float2*)&Y[(size_t)mrow * ldy + ncol]       = make_float2(c[0], c[1]);
                    *(float2*)&Y[(size_t)(mrow + 8) * ldy + ncol] = make_float2(c[2], c[3]);
                } else {
                    uint32_t ph, pl;
                    split2(c[0], c[1], ph, pl);
                    *(uint32_t*)&g_vh[(size_t)mrow * KVD + ncol] = ph;
                    *(uint32_t*)&g_vl[(size_t)mrow * KVD + ncol] = pl;
                    split2(c[2], c[3], ph, pl);
                    *(uint32_t*)&g_vh[(size_t)(mrow + 8) * KVD + ncol] = ph;
                    *(uint32_t*)&g_vl[(size_t)(mrow + 8) * KVD + ncol] = pl;
                }
            }
        }
        return;
    }

    // ---- fused RMS-norm + partial RoPE (+qgain) epilogue (modes 2/3) ----
    float* smsum = (float*)gsm;          // [8 warps][64 rows]
#pragma unroll
    for (int i = 0; i < 4; i++) {
        float s0 = 0.f, s1 = 0.f;
#pragma unroll
        for (int j = 0; j < 4; j++) {
            float* c = acc + (i*4 + j) * 4;
            s0 += c[0]*c[0] + c[1]*c[1];
            s1 += c[2]*c[2] + c[3]*c[3];
        }
        s0 += __shfl_xor_sync(0xffffffffu, s0, 1);
        s0 += __shfl_xor_sync(0xffffffffu, s0, 2);
        s1 += __shfl_xor_sync(0xffffffffu, s1, 1);
        s1 += __shfl_xor_sync(0xffffffffu, s1, 2);
        if (tg == 0) {
            smsum[wid * 64 + i*16 + g]     = s0;
            smsum[wid * 64 + i*16 + g + 8] = s1;
        }
    }
    __syncthreads();
    int pw = wid ^ 2;                     // partner warp: other 32 cols of head
    bool dorope = ((nbase & 32) == 0);    // warp covers head cols 0..31
    float qsc = (mode == 2)
        ? qgain[(n0y + nbase) >> 6] * 0.125f * 1.4426950408889634f : 1.f;

#pragma unroll
    for (int i = 0; i < 4; i++) {
        int rl = i*16 + g;
        float t0 = smsum[wid*64 + rl]     + smsum[pw*64 + rl];
        float t1 = smsum[wid*64 + rl + 8] + smsum[pw*64 + rl + 8];
        float a0 = t0 * (1.0f/64.0f) + 1.1920929e-07f;
        float a1 = t1 * (1.0f/64.0f) + 1.1920929e-07f;
        float r0 = rsqrtf(a0); r0 = r0 * (1.5f - 0.5f * a0 * r0 * r0);
        float r1 = rsqrtf(a1); r1 = r1 * (1.5f - 0.5f * a1 * r1 * r1);
#pragma unroll
        for (int j = 0; j < 4; j++) {
            float* c = acc + (i*4 + j) * 4;
            c[0] *= r0; c[1] *= r0; c[2] *= r1; c[3] *= r1;
        }
        if (dorope) {
            int mrow = m0 + mbase + i*16 + g;
            int ta = mrow & (TT - 1), tb = (mrow + 8) & (TT - 1);
            float* c0 = acc + (i*4 + 0) * 4;   // cols 2tg, 2tg+1 (x1)
            float* c1 = acc + (i*4 + 1) * 4;   // cols 8+2tg, 8+2tg+1 (x2)
            int d0 = 2*tg, d1 = 2*tg + 1;
            float ca0 = g_cos[ta][d0], sa0 = g_sin[ta][d0];
            float ca1 = g_cos[ta][d1], sa1 = g_sin[ta][d1];
            float cb0 = g_cos[tb][d0], sb0 = g_sin[tb][d0];
            float cb1 = g_cos[tb][d1], sb1 = g_sin[tb][d1];
            float x1, x2;
            x1 = c0[0]; x2 = c1[0]; c0[0] = x1*ca0 + x2*sa0; c1[0] = x2*ca0 - x1*sa0;
            x1 = c0[1]; x2 = c1[1]; c0[1] = x1*ca1 + x2*sa1; c1[1] = x2*ca1 - x1*sa1;
            x1 = c0[2]; x2 = c1[2]; c0[2] = x1*cb0 + x2*sb0; c1[2] = x2*cb0 - x1*sb0;
            x1 = c0[3]; x2 = c1[3]; c0[3] = x1*cb1 + x2*sb1; c1[3] = x2*cb1 - x1*sb1;
        }
        if (mode == 2) {
#pragma unroll
            for (int j = 0; j < 4; j++) {
                float* c = acc + (i*4 + j) * 4;
                c[0] *= qsc; c[1] *= qsc; c[2] *= qsc; c[3] *= qsc;
            }
        }
    }

    bf16* dh = (mode == 2) ? g_qh : g_kh;
    bf16* dl = (mode == 2) ? g_ql : g_kl;
#pragma unroll
    for (int i = 0; i < 4; i++) {
#pragma unroll
        for (int j = 0; j < 4; j++) {
            float* c = acc + (i*4 + j) * 4;
            int mrow = m0 + mbase + i*16 + g;
            int ncol = n0y + nbase + j*8 + tg*2;
            uint32_t ph, pl;
            split2(c[0], c[1], ph, pl);
            *(uint32_t*)&dh[(size_t)mrow * ldy + ncol] = ph;
            *(uint32_t*)&dl[(size_t)mrow * ldy + ncol] = pl;
            split2(c[2], c[3], ph, pl);
            *(uint32_t*)&dh[(size_t)(mrow + 8) * ldy + ncol] = ph;
            *(uint32_t*)&dl[(size_t)(mrow + 8) * ldy + ncol] = pl;
        }
    }
}

__global__ __launch_bounds__(256, 2) void qkv_gemm_kernel(const float* __restrict__ qgain) {
    int m0 = blockIdx.x * 128;
    int n0 = blockIdx.y * 128;
    const bf16* Ah = g_xh + (size_t)m0 * CC;
    const bf16* Al = g_xl + (size_t)m0 * CC;
    const bf16* Bh = g_wfh + (size_t)n0 * CC;
    const bf16* Bl = g_wfl + (size_t)n0 * CC;
    if (n0 < CC)
        bf16_gemm_body(Ah, Al, Bh, Bl, nullptr, CC, m0, n0, 2, qgain);           // Q
    else if (n0 < CC + KVD)
        bf16_gemm_body(Ah, Al, Bh, Bl, nullptr, KVD, m0, n0 - CC, 3, nullptr);   // K
    else
        bf16_gemm_body(Ah, Al, Bh, Bl, nullptr, KVD, m0, n0 - CC - KVD, 1, nullptr); // V
}

__global__ __launch_bounds__(256, 2) void proj_gemm_kernel(float* __restrict__ out) {
    int m0 = blockIdx.x * 128;
    int n0 = blockIdx.y * 128;
    bf16_gemm_body(g_ah + (size_t)m0 * CC, g_al + (size_t)m0 * CC,
                   g_wph + (size_t)n0 * CC, g_wpl + (size_t)n0 * CC,
                   out, CC, m0, n0, 0, nullptr);
}

// ---------------- RoPE table (double precision of fp32 angle) ---------------
__global__ void rope_table_kernel() {
    int idx = blockIdx.x * blockDim.x + threadIdx.x;
    if (idx >= TT * 8) return;
    int t = idx >> 3;
    int i = idx & 7;
    double inv_d = exp2(-((double)(2 * i) / 64.0) * 13.28771237954945);
    float inv_f = (float)inv_d;
    float ang = (float)t * inv_f;
    g_cos[t][i] = (float)cos((double)ang);
    g_sin[t][i] = (float)sin((double)ang);
}

// ---------------- flash attention v2: Q in smem, 32-key tiles, 2 CTA/SM ------
#define ASP   72                   // smem row stride (bf16 elems)
#define QARR  (128 * ASP)          // 9216 elems per Q array
#define AKR   32                   // keys per tile
#define AARR  (AKR * ASP)          // 2304 elems per K/V array
#define ASTG  (4 * AARR)           // per stage
#define ATTN_SMEM_BYTES ((2 * QARR + 2 * ASTG) * 2)   // 73728 B

__device__ __forceinline__ void attn_issue(
    const bf16* kh, const bf16* kl, const bf16* vh, const bf16* vl,
    uint32_t sb, int st, int k0)
{
    int tid = threadIdx.x;
    int r   = tid >> 3;                  // key row 0..31
    int s0  = tid & 7;                   // seg 0..7
    size_t go = (size_t)(k0 + r) * KVD + s0 * 8;
    uint32_t d = sb + (uint32_t)(2 * QARR + st * ASTG + r * ASP + s0 * 8) * 2;
    const uint32_t AB = AARR * 2;
    cp16(d,        kh + go);
    cp16(d + AB,   kl + go);
    cp16(d + 2*AB, vh + go);
    cp16(d + 3*AB, vl + go);
}

__device__ __forceinline__ void attn_issue_q(
    const bf16* qh, const bf16* ql, uint32_t sb, int row0)
{
    int tid = threadIdx.x;
    int r   = tid >> 1;                  // q row 0..127
    int s0  = (tid & 1) * 4;             // segs s0..s0+3
    size_t go = (size_t)(row0 + r) * CC + s0 * 8;
    uint32_t d = sb + (uint32_t)(r * ASP + s0 * 8) * 2;
#pragma unroll
    for (int i = 0; i < 4; i++) {
        cp16(d + i * 16,            qh + go + i * 8);
        cp16(d + QARR * 2 + i * 16, ql + go + i * 8);
    }
}

__global__ __launch_bounds__(256, 2) void attn_kernel(const int* __restrict__ wl_ptr) {
    extern __shared__ bf16 asm_[];
    uint32_t sb = smem_u32(asm_);

    int tid  = threadIdx.x;
    int w    = tid >> 5;
    int lane = tid & 31;
    int g    = lane >> 2, tg = lane & 3;
    int ln15 = lane & 15;

    int h  = blockIdx.x & 15;
    int b  = blockIdx.x >> 4;
    int q0 = (int)(gridDim.y - 1 - blockIdx.y) * 128;
    int kvh = h >> 2;

    int wl = *wl_ptr;
    if (wl < 0) wl = TT;

    int qr0   = q0 + w * 16 + g;
    int qr1   = qr0 + 8;
    int qrmin = q0 + w * 16;
    int qrmax = qrmin + 15;

    uint32_t qoff = (uint32_t)((w * 16 + (lane & 15)) * ASP
                               + ((lane >> 4) & 1) * 8) * 2;
    uint32_t koff = (uint32_t)(((lane & 7) + ((lane & 16) ? 8 : 0)) * ASP
                               + ((lane & 8) ? 8 : 0)) * 2;

    float O[8][4];
#pragma unroll
    for (int j = 0; j < 8; j++)
#pragma unroll
        for (int c = 0; c < 4; c++) O[j][c] = 0.f;
    float m0 = -INFINITY, m1 = -INFINITY, l0 = 0.f, l1 = 0.f;

    int lo_b = q0 - wl;
    int kt_lo = (lo_b > 0) ? (lo_b / AKR) : 0;
    int kt_hi = (q0 + 127) / AKR;

    const bf16* kh = g_kh + (size_t)b * TT * KVD + kvh * DD;
    const bf16* kl = g_kl + (size_t)b * TT * KVD + kvh * DD;
    const bf16* vh = g_vh + (size_t)b * TT * KVD + kvh * DD;
    const bf16* vl = g_vl + (size_t)b * TT * KVD + kvh * DD;

    attn_issue_q(g_qh + (size_t)h * DD, g_ql + (size_t)h * DD, sb, b * TT + q0);
    attn_issue(kh, kl, vh, vl, sb, kt_lo & 1, kt_lo * AKR);
    CP_COMMIT();

#pragma unroll 1
    for (int kt = kt_lo; kt <= kt_hi; kt++) {
        int st = kt & 1;
        int k0 = kt * AKR;
        if (kt < kt_hi) {
            attn_issue(kh, kl, vh, vl, sb, st ^ 1, k0 + AKR);
            CP_COMMIT();
            CP_WAIT1();
        } else {
            CP_WAIT0();
        }
        __syncthreads();

        bool live = !(k0 > qrmax || k0 + AKR - 1 < qrmin - wl);
        if (live) {
            // fast path: the whole tile is unmasked for this warp
            bool full = (k0 + AKR - 1 <= qrmin) && (qrmax - k0 <= wl);

            uint32_t kh_a = sb + (uint32_t)(2 * QARR + st * ASTG) * 2;
            uint32_t vh_b = kh_a + 2 * AARR * 2;
            const uint32_t ALO = AARR * 2;
            const uint32_t QLO = QARR * 2;

            float S[4][4];
#pragma unroll
            for (int j = 0; j < 4; j++)
#pragma unroll
                for (int c = 0; c < 4; c++) S[j][c] = 0.f;
#pragma unroll
            for (int s = 0; s < 4; s++) {
                uint32_t aq0, aq1, aq2, aq3, al0, al1, al2, al3;
                ldsm_x4(sb + qoff + s * 32,       aq0, aq1, aq2, aq3);
                ldsm_x4(sb + qoff + QLO + s * 32, al0, al1, al2, al3);
#pragma unroll
                for (int jp = 0; jp < 2; jp++) {
                    uint32_t ab = kh_a + koff + (uint32_t)(jp * 16 * ASP) * 2 + s * 32;
                    uint32_t h0, h1, h2, h3, e0, e1, e2, e3;
                    ldsm_x4(ab,       h0, h1, h2, h3);
                    ldsm_x4(ab + ALO, e0, e1, e2, e3);
                    mma_bf16(S[2*jp],   aq0, aq1, aq2, aq3, h0, h1);
                    mma_bf16(S[2*jp+1], aq0, aq1, aq2, aq3, h2, h3);
                    mma_bf16(S[2*jp],   aq0, aq1, aq2, aq3, e0, e1);
                    mma_bf16(S[2*jp+1], aq0, aq1, aq2, aq3, e2, e3);
                    mma_bf16(S[2*jp],   al0, al1, al2, al3, h0, h1);
                    mma_bf16(S[2*jp+1], al0, al1, al2, al3, h2, h3);
                }
            }

            if (!full) {
                // exact mask on boundary tiles only
#pragma unroll
                for (int j = 0; j < 4; j++) {
                    int kj = k0 + 8 * j + 2 * tg;
                    if (!(kj     <= qr0 && qr0 - kj     <= wl)) S[j][0] = -INFINITY;
                    if (!(kj + 1 <= qr0 && qr0 - kj - 1 <= wl)) S[j][1] = -INFINITY;
                    if (!(kj     <= qr1 && qr1 - kj     <= wl)) S[j][2] = -INFINITY;
                    if (!(kj + 1 <= qr1 && qr1 - kj - 1 <= wl)) S[j][3] = -INFINITY;
                }
            }
            float mc0 = -INFINITY, mc1 = -INFINITY;
#pragma unroll
            for (int j = 0; j < 4; j++) {
                mc0 = fmaxf(mc0, fmaxf(S[j][0], S[j][1]));
                mc1 = fmaxf(mc1, fmaxf(S[j][2], S[j][3]));
            }
            mc0 = fmaxf(mc0, __shfl_xor_sync(0xffffffffu, mc0, 1));
            mc0 = fmaxf(mc0, __shfl_xor_sync(0xffffffffu, mc0, 2));
            mc1 = fmaxf(mc1, __shfl_xor_sync(0xffffffffu, mc1, 1));
            mc1 = fmaxf(mc1, __shfl_xor_sync(0xffffffffu, mc1, 2));

            if (full | (mc0 > -INFINITY)) {
                float mn = fmaxf(m0, mc0);
                float corr = fast_exp2(m0 - mn);
                m0 = mn; l0 *= corr;
                float sum = 0.f;
#pragma unroll
                for (int j = 0; j < 8; j++) { O[j][0] *= corr; O[j][1] *= corr; }
#pragma unroll
                for (int j = 0; j < 4; j++) {
                    S[j][0] = fast_exp2(S[j][0] - m0);
                    S[j][1] = fast_exp2(S[j][1] - m0);
                    sum += S[j][0] + S[j][1];
                }
                l0 += sum;
            } else {
#pragma unroll
                for (int j = 0; j < 4; j++) { S[j][0] = 0.f; S[j][1] = 0.f; }
            }
            if (full | (mc1 > -INFINITY)) {
                float mn = fmaxf(m1, mc1);
                float corr = fast_exp2(m1 - mn);
                m1 = mn; l1 *= corr;
                float sum = 0.f;
#pragma unroll
                for (int j = 0; j < 8; j++) { O[j][2] *= corr; O[j][3] *= corr; }
#pragma unroll
                for (int j = 0; j < 4; j++) {
                    S[j][2] = fast_exp2(S[j][2] - m1);
                    S[j][3] = fast_exp2(S[j][3] - m1);
                    sum += S[j][2] + S[j][3];
                }
                l1 += sum;
            } else {
#pragma unroll
                for (int j = 0; j < 4; j++) { S[j][2] = 0.f; S[j][3] = 0.f; }
            }

            uint32_t pah[2][4], pal[2][4];
#pragma unroll
            for (int s2 = 0; s2 < 2; s2++) {
                split2(S[2*s2][0],   S[2*s2][1],   pah[s2][0], pal[s2][0]);
                split2(S[2*s2][2],   S[2*s2][3],   pah[s2][1], pal[s2][1]);
                split2(S[2*s2+1][0], S[2*s2+1][1], pah[s2][2], pal[s2][2]);
                split2(S[2*s2+1][2], S[2*s2+1][3], pah[s2][3], pal[s2][3]);
            }
#pragma unroll
            for (int s2 = 0; s2 < 2; s2++) {
                uint32_t rowh4 = vh_b + (uint32_t)((16 * s2 + ln15) * (ASP * 2))
                               + ((uint32_t)(lane >> 4) << 4);
#pragma unroll
                for (int j = 0; j < 8; j += 2) {
                    uint32_t bh0, bh1, bh2, bh3, bl0, bl1, bl2, bl3;
                    ldsm_x4_t(rowh4 + 16 * j,       bh0, bh1, bh2, bh3);
                    ldsm_x4_t(rowh4 + ALO + 16 * j, bl0, bl1, bl2, bl3);
                    mma_bf16(O[j],   pah[s2][0], pah[s2][1], pah[s2][2], pah[s2][3], bh0, bh1);
                    mma_bf16(O[j+1], pah[s2][0], pah[s2][1], pah[s2][2], pah[s2][3], bh2, bh3);
                    mma_bf16(O[j],   pah[s2][0], pah[s2][1], pah[s2][2], pah[s2][3], bl0, bl1);
                    mma_bf16(O[j+1], pah[s2][0], pah[s2][1], pah[s2][2], pah[s2][3], bl2, bl3);
                    mma_bf16(O[j],   pal[s2][0], pal[s2][1], pal[s2][2], pal[s2][3], bh0, bh1);
                    mma_bf16(O[j+1], pal[s2][0], pal[s2][1], pal[s2][2], pal[s2][3], bh2, bh3);
                }
            }
        }
        __syncthreads();
    }

    l0 += __shfl_xor_sync(0xffffffffu, l0, 1);
    l0 += __shfl_xor_sync(0xffffffffu, l0, 2);
    l1 += __shfl_xor_sync(0xffffffffu, l1, 1);
    l1 += __shfl_xor_sync(0xffffffffu, l1, 2);
    float inv0 = 1.0f / l0;
    float inv1 = 1.0f / l1;
    size_t ro0 = (size_t)(b * TT + qr0) * CC + h * DD;
    size_t ro1 = ro0 + 8 * CC;
#pragma unroll
    for (int j = 0; j < 8; j++) {
        int col = 8 * j + 2 * tg;
        uint32_t ph, pl;
        split2(O[j][0] * inv0, O[j][1] * inv0, ph, pl);
        *(uint32_t*)&g_ah[ro0 + col] = ph;
        *(uint32_t*)&g_al[ro0 + col] = pl;
        split2(O[j][2] * inv1, O[j][3] * inv1, ph, pl);
        *(uint32_t*)&g_ah[ro1 + col] = ph;
        *(uint32_t*)&g_al[ro1 + col] = pl;
    }
}

// ---------------- launch -----------------------------------------------------
extern "C" void kernel_launch(void* const* d_in, const int* in_sizes, int n_in,
                              void* d_out, int out_size) {
    const float* x     = (const float*)d_in[0];
    const float* wq    = (const float*)d_in[1];
    const float* wk    = (const float*)d_in[2];
    const float* wv    = (const float*)d_in[3];
    const float* wproj = (const float*)d_in[4];
    const float* qgain = (const float*)d_in[5];
    const int*   wl    = (const int*)d_in[6];
    float* out = (float*)d_out;

    cudaFuncSetAttribute(qkv_gemm_kernel,
                         cudaFuncAttributeMaxDynamicSharedMemorySize, GEMM_SMEM_BYTES);
    cudaFuncSetAttribute(proj_gemm_kernel,
                         cudaFuncAttributeMaxDynamicSharedMemorySize, GEMM_SMEM_BYTES);
    cudaFuncSetAttribute(attn_kernel,
                         cudaFuncAttributeMaxDynamicSharedMemorySize, ATTN_SMEM_BYTES);

    rope_table_kernel<<<(TT * 8 + 255) / 256, 256>>>();

    const int NQUAD = MM*CC/4 + CC*CC/4 + KVD*CC/4 + KVD*CC/4 + CC*CC/4;
    cvt_all_kernel<<<(NQUAD + 255) / 256, 256>>>(x, wq, wk, wv, wproj);

    dim3 g1(MM / 128, NW / 128);               // 32 x 12
    qkv_gemm_kernel<<<g1, 256, GEMM_SMEM_BYTES>>>(qgain);

    dim3 g2(HH * BB, TT / 128);                // 32 x 16
    attn_kernel<<<g2, 256, ATTN_SMEM_BYTES>>>(wl);

    dim3 g3(MM / 128, CC / 128);               // 32 x 8
    proj_gemm_kernel<<<g3, 256, GEMM_SMEM_BYTES>>>(out);
}